// round 5
// baseline (speedup 1.0000x reference)
#include <cuda_runtime.h>
#include <cuda_fp16.h>

// x: [8,32,512] fp32, w_q/w_k/w_v: [1,128] fp32, out: [8,32,128] fp32
#define BV      256
#define FDIM    512
#define DMODEL  128
#define SUBS    8        // blocks per row: 8 = (8 f-chunks of 64) x (g split below)
#define FC      64       // f per block
#define TPB     128      // 64 f  x  2 g-halves

__device__ float    g_partial[BV * SUBS];
__device__ unsigned g_cnt[BV];          // zero-init; self-resetting per launch

__device__ __forceinline__ __half2 ex2_h2(__half2 a) {
    unsigned r, u = *(unsigned*)&a;
    asm("ex2.approx.f16x2 %0, %1;" : "=r"(r) : "r"(u));
    return *(__half2*)&r;
}
__device__ __forceinline__ float ldcg(const float* p) {
    float v;
    asm volatile("ld.global.cg.f32 %0, [%1];" : "=f"(v) : "l"(p));
    return v;
}

__global__ __launch_bounds__(TPB)
void attn_fused_kernel(const float* __restrict__ x,
                       const float* __restrict__ wq,
                       const float* __restrict__ wk,
                       const float* __restrict__ wv,
                       float* __restrict__ out)
{
    __shared__ __align__(16) float   sx[FDIM];
    __shared__ __align__(16) __half2 sdmax[FDIM / 2];  // half2(x - xmax)
    __shared__ __align__(16) __half2 sdmin[FDIM / 2];  // half2(x - xmin)
    __shared__ float sDen[TPB];
    __shared__ float sNum[TPB];
    __shared__ float sRed[12];
    __shared__ float sK, sMax, sMin;
    __shared__ int   sLast;

    const int tid   = threadIdx.x;
    const int lane  = tid & 31;
    const int warp  = tid >> 5;
    const int bv    = blockIdx.x >> 3;
    const int sub   = blockIdx.x & 7;        // f-chunk of 64
    const int fi    = tid & 63;              // f within chunk
    const int gh    = tid >> 6;              // g half (0/1)
    const float* __restrict__ xr = x + bv * FDIM;

    // Stage row into smem (fp32), track row max/min.
    float lmax = -3.402823466e38f, lmin = 3.402823466e38f;
    #pragma unroll
    for (int i = 0; i < FDIM / TPB; i++) {
        float v = xr[tid + TPB * i];
        sx[tid + TPB * i] = v;
        lmax = fmaxf(lmax, v);
        lmin = fminf(lmin, v);
    }
    float p = wq[tid] * wk[tid];
    #pragma unroll
    for (int s = 16; s > 0; s >>= 1) {
        p   += __shfl_xor_sync(~0u, p, s);
        lmax = fmaxf(lmax, __shfl_xor_sync(~0u, lmax, s));
        lmin = fminf(lmin, __shfl_xor_sync(~0u, lmin, s));
    }
    if (lane == 0) { sRed[warp] = p; sRed[4 + warp] = lmax; sRed[8 + warp] = lmin; }
    __syncthreads();
    if (tid == 0) {
        float P  = sRed[0] + sRed[1] + sRed[2] + sRed[3];
        float Mx = fmaxf(fmaxf(sRed[4], sRed[5]), fmaxf(sRed[6], sRed[7]));
        float Mn = fminf(fminf(sRed[8], sRed[9]), fminf(sRed[10], sRed[11]));
        sK   = P * (1.4426950408889634f * 0.08838834764831845f); // log2(e)/sqrt(128)
        sMax = Mx;
        sMin = Mn;
    }
    __syncthreads();
    const float xmax = sMax, xmin = sMin;

    // Precompute half2 deviation rows.
    #pragma unroll
    for (int j = tid; j < FDIM / 2; j += TPB) {
        float a = sx[2 * j], b = sx[2 * j + 1];
        sdmax[j] = __floats2half2_rn(a - xmax, b - xmax);
        sdmin[j] = __floats2half2_rn(a - xmin, b - xmin);
    }
    __syncthreads();

    // logit = t2*(x_g - x_ext); this thread covers 256 g of one f.
    const float xf   = sx[sub * FC + fi];
    const float t2   = sK * xf;
    const bool  pos  = (t2 >= 0.0f);
    const float xext = pos ? xmax : xmin;
    // 256 g = 32 uint4; offset by g-half.
    const uint4* __restrict__ d4 = (const uint4*)(pos ? sdmax : sdmin) + gh * 32;
    const __half2 t2h = __float2half2_rn(t2);

    float den = 0.0f, nump = 0.0f;   // s_f = nump/den + xext
    #pragma unroll 4
    for (int blk = 0; blk < 16; blk++) {        // 16 blocks x 16 g
        uint4 a = d4[2 * blk];                  // smem broadcast within warp
        uint4 b = d4[2 * blk + 1];
        __half2 dv0 = *(__half2*)&a.x, dv1 = *(__half2*)&a.y;
        __half2 dv2 = *(__half2*)&a.z, dv3 = *(__half2*)&a.w;
        __half2 dv4 = *(__half2*)&b.x, dv5 = *(__half2*)&b.y;
        __half2 dv6 = *(__half2*)&b.z, dv7 = *(__half2*)&b.w;

        __half2 e0 = ex2_h2(__hmul2(t2h, dv0));
        __half2 e1 = ex2_h2(__hmul2(t2h, dv1));
        __half2 e2 = ex2_h2(__hmul2(t2h, dv2));
        __half2 e3 = ex2_h2(__hmul2(t2h, dv3));
        __half2 e4 = ex2_h2(__hmul2(t2h, dv4));
        __half2 e5 = ex2_h2(__hmul2(t2h, dv5));
        __half2 e6 = ex2_h2(__hmul2(t2h, dv6));
        __half2 e7 = ex2_h2(__hmul2(t2h, dv7));

        __half2 dh0 = __hadd2(__hadd2(e0, e1), __hadd2(e2, e3));
        __half2 dh1 = __hadd2(__hadd2(e4, e5), __hadd2(e6, e7));
        __half2 nh0 = __hmul2(e0, dv0);
        nh0 = __hfma2(e1, dv1, nh0);
        nh0 = __hfma2(e2, dv2, nh0);
        nh0 = __hfma2(e3, dv3, nh0);
        __half2 nh1 = __hmul2(e4, dv4);
        nh1 = __hfma2(e5, dv5, nh1);
        nh1 = __hfma2(e6, dv6, nh1);
        nh1 = __hfma2(e7, dv7, nh1);

        float2 dd0 = __half22float2(dh0), dd1 = __half22float2(dh1);
        float2 nn0 = __half22float2(nh0), nn1 = __half22float2(nh1);
        den  += (dd0.x + dd0.y) + (dd1.x + dd1.y);
        nump += (nn0.x + nn0.y) + (nn1.x + nn1.y);
    }

    // Combine the two g-halves of each f, then ratio, then reduce over 64 f.
    sDen[tid] = den;
    sNum[tid] = nump;
    __syncthreads();
    float partial = 0.0f;
    if (tid < FC) {
        float dTot = sDen[tid] + sDen[tid + FC];
        float nTot = sNum[tid] + sNum[tid + FC];
        partial = nTot / dTot + xext;            // s_f
        #pragma unroll
        for (int s = 16; s > 0; s >>= 1)
            partial += __shfl_xor_sync(~0u, partial, s);
        if (lane == 0) sRed[warp] = partial;     // warps 0,1
    }
    __syncthreads();

    // Fused finalize via ticket over the 8 sub-blocks of this row.
    if (tid == 0) {
        g_partial[blockIdx.x] = sRed[0] + sRed[1];
        __threadfence();
        unsigned old = atomicAdd(&g_cnt[bv], 1u);
        sLast = (old == SUBS - 1);
        if (sLast) __threadfence();
    }
    __syncthreads();
    if (sLast) {
        float m = 0.0f;
        #pragma unroll
        for (int i = 0; i < SUBS; i++)
            m += ldcg(&g_partial[bv * SUBS + i]);
        m *= (1.0f / 512.0f);
        out[bv * DMODEL + tid] = m * wv[tid];
        if (tid == 0) g_cnt[bv] = 0;
    }
}

extern "C" void kernel_launch(void* const* d_in, const int* in_sizes, int n_in,
                              void* d_out, int out_size)
{
    const float* x  = (const float*)d_in[0];
    const float* wq = (const float*)d_in[1];
    const float* wk = (const float*)d_in[2];
    const float* wv = (const float*)d_in[3];
    float* out = (float*)d_out;

    attn_fused_kernel<<<BV * SUBS, TPB>>>(x, wq, wk, wv, out);
}